// round 7
// baseline (speedup 1.0000x reference)
#include <cuda_runtime.h>
#include <cuda_fp16.h>
#include <cstdint>
#include <math.h>

// Problem constants
#define T_TOK 4096
#define HDIM  2048
#define FDIM  4096
#define NEXP  8
#define TOPK  2
#define NASSIGN (T_TOK * TOPK)   // 8192

// GEMM tiling
#define BM 128
#define BN 256
#define BK 64
#define MTILES_MAX 16

#define A_ROW_B 144              // 64 fp16 = 128B + 16B pad
#define B_ROW_B 528              // 256 fp16 = 512B + 16B pad
#define OFF_B   (BM * A_ROW_B)               // 18432
#define STAGE_B (OFF_B + BK * B_ROW_B)       // 52224
#define NSTAGE  3
#define SMEM_TOTAL (NSTAGE * STAGE_B)        // 156672
#define EP_STRIDE_B 112          // epilogue smem row stride

// ---------------------------------------------------------------------------
// Scratch
// ---------------------------------------------------------------------------
__device__ __half g_x[(size_t)T_TOK * HDIM];
// w1 fp16, column-interleaved: [E][H][2F], col n' = 2f -> a_f, 2f+1 -> b_f
__device__ __half g_w1i[(size_t)NEXP * HDIM * 2 * FDIM];
// w2 fp16, natural layout [E][F][H]
__device__ __half g_w2s[(size_t)NEXP * FDIM * HDIM];
// swiglu output fp16: [NASSIGN][F]
__device__ __half g_s[(size_t)NASSIGN * FDIM];

__device__ int   g_eid[T_TOK * TOPK];
__device__ float g_wt [T_TOK * TOPK];
__device__ int   g_tok[NASSIGN];
__device__ float g_w  [NASSIGN];
__device__ int   g_cnt [NEXP];
__device__ int   g_off [NEXP + 1];
__device__ int   g_fill[NEXP];

// ---------------------------------------------------------------------------
// PTX helpers (base ISA only — valid on plain sm_103 target)
// ---------------------------------------------------------------------------
__device__ __forceinline__ void cp16(uint32_t dst, const void* src, uint32_t sz) {
    asm volatile("cp.async.cg.shared.global [%0], [%1], 16, %2;"
                 :: "r"(dst), "l"(src), "r"(sz) : "memory");
}
__device__ __forceinline__ void cp_commit() {
    asm volatile("cp.async.commit_group;" ::: "memory");
}
__device__ __forceinline__ void cp_wait1() {
    asm volatile("cp.async.wait_group 1;" ::: "memory");
}
__device__ __forceinline__ void cp_wait0() {
    asm volatile("cp.async.wait_group 0;" ::: "memory");
}
__device__ __forceinline__ void ldsm4(uint32_t* r, uint32_t a) {
    asm volatile("ldmatrix.sync.aligned.m8n8.x4.shared.b16 {%0,%1,%2,%3}, [%4];"
                 : "=r"(r[0]), "=r"(r[1]), "=r"(r[2]), "=r"(r[3]) : "r"(a));
}
__device__ __forceinline__ void ldsm4t(uint32_t* r, uint32_t a) {
    asm volatile("ldmatrix.sync.aligned.m8n8.x4.trans.shared.b16 {%0,%1,%2,%3}, [%4];"
                 : "=r"(r[0]), "=r"(r[1]), "=r"(r[2]), "=r"(r[3]) : "r"(a));
}
__device__ __forceinline__ void mma4(float* c, const uint32_t* a, uint32_t b0, uint32_t b1) {
    asm volatile("mma.sync.aligned.m16n8k16.row.col.f32.f16.f16.f32 "
                 "{%0,%1,%2,%3}, {%4,%5,%6,%7}, {%8,%9}, {%0,%1,%2,%3};"
                 : "+f"(c[0]), "+f"(c[1]), "+f"(c[2]), "+f"(c[3])
                 : "r"(a[0]), "r"(a[1]), "r"(a[2]), "r"(a[3]), "r"(b0), "r"(b1));
}

// ---------------------------------------------------------------------------
// 0) reset output (runs after routing, before gemm2 — the only consumer)
// ---------------------------------------------------------------------------
__global__ void reset_kernel(float* __restrict__ out) {
    size_t i = (size_t)blockIdx.x * blockDim.x + threadIdx.x;
    out[i] = 0.0f;  // grid sized exactly T_TOK*HDIM
}

// ---------------------------------------------------------------------------
// 1) convert x (launch #1; also zeroes expert counters for this replay)
// ---------------------------------------------------------------------------
__global__ void convert_x_kernel(const float* __restrict__ x) {
    if (blockIdx.x == 0 && threadIdx.x < NEXP) g_cnt[threadIdx.x] = 0;
    size_t i = ((size_t)blockIdx.x * blockDim.x + threadIdx.x) * 8;
    float4 v0 = *reinterpret_cast<const float4*>(x + i);
    float4 v1 = *reinterpret_cast<const float4*>(x + i + 4);
    __half h[8];
    h[0] = __float2half_rn(v0.x); h[1] = __float2half_rn(v0.y);
    h[2] = __float2half_rn(v0.z); h[3] = __float2half_rn(v0.w);
    h[4] = __float2half_rn(v1.x); h[5] = __float2half_rn(v1.y);
    h[6] = __float2half_rn(v1.z); h[7] = __float2half_rn(v1.w);
    *reinterpret_cast<uint4*>(g_x + i) = *reinterpret_cast<uint4*>(h);
}

// ---------------------------------------------------------------------------
// 2) gate: top-2 + softmax in fp32 (exact routing — proven)
// ---------------------------------------------------------------------------
__global__ void gate_kernel(const float* __restrict__ x, const float* __restrict__ gw) {
    int warp = threadIdx.x >> 5, lane = threadIdx.x & 31;
    int t = blockIdx.x * (blockDim.x >> 5) + warp;
    if (t >= T_TOK) return;
    float acc[NEXP];
#pragma unroll
    for (int e = 0; e < NEXP; e++) acc[e] = 0.0f;
    const float* xp = x + (size_t)t * HDIM;
    for (int h = lane; h < HDIM; h += 32) {
        float xv = xp[h];
#pragma unroll
        for (int e = 0; e < NEXP; e++) acc[e] += xv * gw[e * HDIM + h];
    }
#pragma unroll
    for (int e = 0; e < NEXP; e++)
#pragma unroll
        for (int o = 16; o > 0; o >>= 1)
            acc[e] += __shfl_xor_sync(0xffffffffu, acc[e], o);
    if (lane == 0) {
        int e0 = 0; float l0 = acc[0];
#pragma unroll
        for (int e = 1; e < NEXP; e++) if (acc[e] > l0) { l0 = acc[e]; e0 = e; }
        int e1 = -1; float l1 = -INFINITY;
#pragma unroll
        for (int e = 0; e < NEXP; e++) if (e != e0 && acc[e] > l1) { l1 = acc[e]; e1 = e; }
        float p = expf(l1 - l0);
        float s = 1.0f / (1.0f + p);
        g_eid[2 * t] = e0;  g_eid[2 * t + 1] = e1;
        g_wt [2 * t] = s;   g_wt [2 * t + 1] = p * s;
        atomicAdd(&g_cnt[e0], 1);
        atomicAdd(&g_cnt[e1], 1);
    }
}

__global__ void scan_kernel() {
    int s = 0;
    for (int e = 0; e < NEXP; e++) { g_off[e] = s; s += g_cnt[e]; g_fill[e] = 0; }
    g_off[NEXP] = s;
}

__global__ void scatter_kernel() {
    int t = blockIdx.x * blockDim.x + threadIdx.x;
    if (t >= T_TOK) return;
#pragma unroll
    for (int k = 0; k < TOPK; k++) {
        int e = g_eid[2 * t + k];
        int pos = g_off[e] + atomicAdd(&g_fill[e], 1);
        g_tok[pos] = t;
        g_w[pos]   = g_wt[2 * t + k];
    }
}

// ---------------------------------------------------------------------------
// 3) weight conversions: fp32 -> fp16
// ---------------------------------------------------------------------------
// w1 [E][H][2F]: interleave a/b columns -> fp16
__global__ void convert_w1i_kernel(const float* __restrict__ w1) {
    size_t i = (size_t)blockIdx.x * blockDim.x + threadIdx.x; // over E*H*(F/4)
    size_t ek = i / (FDIM / 4);
    int f0 = (int)(i % (FDIM / 4)) * 4;
    const float* src = w1 + ek * (size_t)(2 * FDIM);
    float4 va = *reinterpret_cast<const float4*>(src + f0);
    float4 vb = *reinterpret_cast<const float4*>(src + FDIM + f0);
    __half h[8];
    h[0] = __float2half_rn(va.x); h[1] = __float2half_rn(vb.x);
    h[2] = __float2half_rn(va.y); h[3] = __float2half_rn(vb.y);
    h[4] = __float2half_rn(va.z); h[5] = __float2half_rn(vb.z);
    h[6] = __float2half_rn(va.w); h[7] = __float2half_rn(vb.w);
    size_t o = ek * (size_t)(2 * FDIM) + 2 * f0;
    *reinterpret_cast<uint4*>(g_w1i + o) = *reinterpret_cast<uint4*>(h);
}

// w2 [E][F][H]: elementwise fp16
__global__ void convert_w2s_kernel(const float* __restrict__ w2) {
    size_t i = ((size_t)blockIdx.x * blockDim.x + threadIdx.x) * 8;
    float4 v0 = *reinterpret_cast<const float4*>(w2 + i);
    float4 v1 = *reinterpret_cast<const float4*>(w2 + i + 4);
    __half h[8];
    h[0] = __float2half_rn(v0.x); h[1] = __float2half_rn(v0.y);
    h[2] = __float2half_rn(v0.z); h[3] = __float2half_rn(v0.w);
    h[4] = __float2half_rn(v1.x); h[5] = __float2half_rn(v1.y);
    h[6] = __float2half_rn(v1.z); h[7] = __float2half_rn(v1.w);
    *reinterpret_cast<uint4*>(g_w2s + i) = *reinterpret_cast<uint4*>(h);
}

// ---------------------------------------------------------------------------
// 4) grouped HMMA GEMM, fp16, BK=64, 3-stage cp.async,
//    register double-buffered ldmatrix fragments across ko.
//    G1=true : D = gather(x) @ w1i, fused swiglu -> g_s (fp16, vectorized)
//    G1=false: Y = S @ w2,          weighted atomic scatter -> out
// ---------------------------------------------------------------------------
template<bool G1>
__global__ __launch_bounds__(256) void gemm_tc(float* __restrict__ out) {
    constexpr int KDIM = G1 ? HDIM : FDIM;
    constexpr int NCH  = KDIM / BK;
    constexpr int LDB  = G1 ? (2 * FDIM) : HDIM;

    const int tid = threadIdx.x;
    const int e = blockIdx.z;
    const int row0 = g_off[e];
    const int nrows = g_off[e + 1] - row0;
    const int mbase = blockIdx.y * BM;
    if (mbase >= nrows) return;
    const int nbase = blockIdx.x * BN;

    extern __shared__ __align__(128) char dsm[];
    const uint32_t smem0 = (uint32_t)__cvta_generic_to_shared(dsm);

    // ---- loader setup: A = 128x64 fp16 (4 x 16B per thread) ----
    const __half* aptr[4];
    uint32_t adst[4], asz[4];
#pragma unroll
    for (int r = 0; r < 4; r++) {
        int idx = tid + 256 * r;
        int m = idx >> 3, cq = idx & 7;
        int gm = mbase + m;
        bool ok = gm < nrows;
        int rowid = ok ? (row0 + gm) : 0;
        if (G1) {
            int tok = ok ? g_tok[rowid] : 0;
            aptr[r] = g_x + (size_t)tok * HDIM + cq * 8;
        } else {
            aptr[r] = g_s + (size_t)rowid * FDIM + cq * 8;
        }
        adst[r] = (uint32_t)(m * A_ROW_B + cq * 16);
        asz[r] = ok ? 16u : 0u;
    }
    // B = 64x256 fp16 (8 x 16B per thread)
    const __half* bptr[8];
    uint32_t bdst[8];
#pragma unroll
    for (int j = 0; j < 8; j++) {
        int idx = tid + 256 * j;
        int row = idx >> 5, cq = idx & 31;
        size_t o;
        if (G1) o = ((size_t)e * HDIM + row) * (size_t)(2 * FDIM) + nbase + cq * 8;
        else    o = ((size_t)e * FDIM + row) * (size_t)HDIM + nbase + cq * 8;
        bptr[j] = (G1 ? g_w1i : g_w2s) + o;
        bdst[j] = (uint32_t)(OFF_B + row * B_ROW_B + cq * 16);
    }

    auto load_stage = [&](int ck) {
        uint32_t sb = smem0 + (ck % NSTAGE) * STAGE_B;
        size_t ka = (size_t)ck * BK;
        size_t kb = (size_t)ck * BK * LDB;
#pragma unroll
        for (int r = 0; r < 4; r++)
            cp16(sb + adst[r], aptr[r] + ka, asz[r]);
#pragma unroll
        for (int j = 0; j < 8; j++)
            cp16(sb + bdst[j], bptr[j] + kb, 16u);
    };

    float c[4][8][4];
#pragma unroll
    for (int i = 0; i < 4; i++)
#pragma unroll
        for (int j = 0; j < 8; j++)
#pragma unroll
            for (int q = 0; q < 4; q++) c[i][j][q] = 0.0f;

    const int lane = tid & 31, wid = tid >> 5;
    const int wm = wid >> 2, wn = wid & 3;
    const int lr = lane & 15, lc = lane >> 4;

    // double-buffered fragments
    uint32_t afr[2][4][4], bfr[2][4][4];
    auto load_frags = [&](int ko, int pb, uint32_t sb) {
        uint32_t aA = sb + (wm * 64 + lr) * A_ROW_B + ko * 32 + lc * 16;
        uint32_t aB = sb + OFF_B + (ko * 16 + lr) * B_ROW_B + wn * 128 + lc * 16;
#pragma unroll
        for (int nj = 0; nj < 4; nj++) ldsm4t(bfr[pb][nj], aB + nj * 32);
#pragma unroll
        for (int mi = 0; mi < 4; mi++) ldsm4(afr[pb][mi], aA + mi * 16 * A_ROW_B);
    };

    load_stage(0); cp_commit();
    load_stage(1); cp_commit();

    for (int ck = 0; ck < NCH; ck++) {
        cp_wait1();
        __syncthreads();
        uint32_t sb = smem0 + (ck % NSTAGE) * STAGE_B;
        load_frags(0, 0, sb);                 // prime ko=0 frags ASAP
        if (ck + 2 < NCH) load_stage(ck + 2); // then hide gmem prefetch
        cp_commit();

#pragma unroll
        for (int ko = 0; ko < 4; ko++) {
            const int cur = ko & 1;
            if (ko < 3) load_frags(ko + 1, cur ^ 1, sb);  // prefetch next frags
#pragma unroll
            for (int mi = 0; mi < 4; mi++)
#pragma unroll
                for (int nj = 0; nj < 4; nj++) {
                    mma4(c[mi][2 * nj],     afr[cur][mi], bfr[cur][nj][0], bfr[cur][nj][1]);
                    mma4(c[mi][2 * nj + 1], afr[cur][mi], bfr[cur][nj][2], bfr[cur][nj][3]);
                }
        }
    }
    cp_wait0();
    __syncthreads();   // all compute done -> smem reusable for epilogue staging

    // ---- epilogue ----
    if constexpr (G1) {
        // swiglu on interleaved (a,b) pairs, stage through smem, vector stores
        __half* ep = reinterpret_cast<__half*>(dsm + wid * 64 * EP_STRIDE_B);
        const int q = lane & 3, lrow = lane >> 2;
#pragma unroll
        for (int mi = 0; mi < 4; mi++) {
            int r0 = mi * 16 + lrow;
#pragma unroll
            for (int n8 = 0; n8 < 8; n8++) {
                int col = n8 * 4 + q;
                float a0 = c[mi][n8][0], b0 = c[mi][n8][1];
                float a1 = c[mi][n8][2], b1 = c[mi][n8][3];
                float s0 = a0 / (1.0f + expf(-a0)) * b0;
                float s1 = a1 / (1.0f + expf(-a1)) * b1;
                *reinterpret_cast<__half*>(
                    reinterpret_cast<char*>(ep) + r0 * EP_STRIDE_B + col * 2) =
                    __float2half_rn(s0);
                *reinterpret_cast<__half*>(
                    reinterpret_cast<char*>(ep) + (r0 + 8) * EP_STRIDE_B + col * 2) =
                    __float2half_rn(s1);
            }
        }
        __syncwarp();
        const int fb = (nbase >> 1) + wn * 32;
#pragma unroll
        for (int j = 0; j < 8; j++) {
            int row = j * 8 + lrow;
            int gm = mbase + wm * 64 + row;
            if (gm < nrows) {
                uint4 v = *reinterpret_cast<const uint4*>(
                    reinterpret_cast<char*>(ep) + row * EP_STRIDE_B + q * 16);
                *reinterpret_cast<uint4*>(
                    &g_s[(size_t)(row0 + gm) * FDIM + fb + q * 8]) = v;
            }
        }
    } else {
        const int q = lane & 3, lrow = lane >> 2;
#pragma unroll
        for (int mi = 0; mi < 4; mi++) {
            int r0 = wm * 64 + mi * 16 + lrow;
            int gm0 = mbase + r0, gm1 = gm0 + 8;
            bool ok0 = gm0 < nrows, ok1 = gm1 < nrows;
            int tok0 = ok0 ? g_tok[row0 + gm0] : 0;
            int tok1 = ok1 ? g_tok[row0 + gm1] : 0;
            float w0 = ok0 ? g_w[row0 + gm0] : 0.0f;
            float w1v = ok1 ? g_w[row0 + gm1] : 0.0f;
            float* o0 = out + (size_t)tok0 * HDIM;
            float* o1 = out + (size_t)tok1 * HDIM;
#pragma unroll
            for (int n8 = 0; n8 < 8; n8++) {
                int col = nbase + wn * 64 + n8 * 8 + q * 2;
                if (ok0) {
                    atomicAdd(o0 + col,     w0 * c[mi][n8][0]);
                    atomicAdd(o0 + col + 1, w0 * c[mi][n8][1]);
                }
                if (ok1) {
                    atomicAdd(o1 + col,     w1v * c[mi][n8][2]);
                    atomicAdd(o1 + col + 1, w1v * c[mi][n8][3]);
                }
            }
        }
    }
}

// ---------------------------------------------------------------------------
// launch — ordered so gemm_tc<true> is the 6th launch (ncu -s 5 -c 1 target)
// ---------------------------------------------------------------------------
extern "C" void kernel_launch(void* const* d_in, const int* in_sizes, int n_in,
                              void* d_out, int out_size) {
    const float* x  = (const float*)d_in[0]; // [T, H]
    const float* gw = (const float*)d_in[1]; // [E, H]
    const float* w1 = (const float*)d_in[2]; // [E, H, 2F]
    const float* w2 = (const float*)d_in[3]; // [E, F, H]
    float* out = (float*)d_out;              // [T, H]

    cudaFuncSetAttribute(gemm_tc<true>,  cudaFuncAttributeMaxDynamicSharedMemorySize, SMEM_TOTAL);
    cudaFuncSetAttribute(gemm_tc<false>, cudaFuncAttributeMaxDynamicSharedMemorySize, SMEM_TOTAL);

    // #1: x conversion (+ counter zeroing)
    convert_x_kernel<<<(T_TOK * HDIM / 8) / 256, 256>>>(x);
    // #2-#4: routing
    gate_kernel<<<T_TOK / 8, 256>>>(x, gw);
    scan_kernel<<<1, 1>>>();
    scatter_kernel<<<T_TOK / 256, 256>>>();
    // #5: w1 conversion
    convert_w1i_kernel<<<(NEXP * HDIM * (FDIM / 4)) / 256, 256>>>(w1);
    // #6: GEMM1 (ncu capture target)
    gemm_tc<true ><<<dim3(2 * FDIM / BN, MTILES_MAX, NEXP), 256, SMEM_TOTAL>>>(out);
    // #7-#8: out reset + w2 conversion
    reset_kernel<<<8192, 1024>>>(out);
    convert_w2s_kernel<<<(int)(((size_t)NEXP * FDIM * HDIM / 8) / 256), 256>>>(w2);
    // #9: GEMM2
    gemm_tc<false><<<dim3(HDIM / BN, MTILES_MAX, NEXP), 256, SMEM_TOTAL>>>(out);
}

// round 8
// speedup vs baseline: 1.0863x; 1.0863x over previous
#include <cuda_runtime.h>
#include <cuda_fp16.h>
#include <cstdint>
#include <math.h>

// Problem constants
#define T_TOK 4096
#define HDIM  2048
#define FDIM  4096
#define NEXP  8
#define TOPK  2
#define NASSIGN (T_TOK * TOPK)   // 8192

// GEMM tiling: 128x128x64, 2 CTAs/SM
#define BM 128
#define BN 128
#define BK 64
#define MTILES_MAX 16

#define A_ROW_B 144              // 64 fp16 = 128B + 16B pad
#define B_ROW_B 272              // 128 fp16 = 256B + 16B pad
#define OFF_B   (BM * A_ROW_B)               // 18432
#define STAGE_B (OFF_B + BK * B_ROW_B)       // 35840
#define NSTAGE  3
#define SMEM_TOTAL (NSTAGE * STAGE_B)        // 107520 -> 2 CTAs/SM
#define EPS 48                   // G1 epilogue smem row stride (32B data + 16 pad)

// ---------------------------------------------------------------------------
// Scratch
// ---------------------------------------------------------------------------
__device__ __half g_x[(size_t)T_TOK * HDIM];
// w1 fp16, column-interleaved: [E][H][2F], col n' = 2f -> a_f, 2f+1 -> b_f
__device__ __half g_w1i[(size_t)NEXP * HDIM * 2 * FDIM];
// w2 fp16, natural layout [E][F][H]
__device__ __half g_w2s[(size_t)NEXP * FDIM * HDIM];
// swiglu output fp16: [NASSIGN][F]
__device__ __half g_s[(size_t)NASSIGN * FDIM];

__device__ int   g_eid[T_TOK * TOPK];
__device__ float g_wt [T_TOK * TOPK];
__device__ int   g_tok[NASSIGN];
__device__ float g_w  [NASSIGN];
__device__ int   g_cnt [NEXP];
__device__ int   g_off [NEXP + 1];
__device__ int   g_fill[NEXP];

// ---------------------------------------------------------------------------
// PTX helpers (base ISA only)
// ---------------------------------------------------------------------------
__device__ __forceinline__ void cp16(uint32_t dst, const void* src, uint32_t sz) {
    asm volatile("cp.async.cg.shared.global [%0], [%1], 16, %2;"
                 :: "r"(dst), "l"(src), "r"(sz) : "memory");
}
__device__ __forceinline__ void cp_commit() {
    asm volatile("cp.async.commit_group;" ::: "memory");
}
__device__ __forceinline__ void cp_wait1() {
    asm volatile("cp.async.wait_group 1;" ::: "memory");
}
__device__ __forceinline__ void cp_wait0() {
    asm volatile("cp.async.wait_group 0;" ::: "memory");
}
__device__ __forceinline__ void ldsm4(uint32_t* r, uint32_t a) {
    asm volatile("ldmatrix.sync.aligned.m8n8.x4.shared.b16 {%0,%1,%2,%3}, [%4];"
                 : "=r"(r[0]), "=r"(r[1]), "=r"(r[2]), "=r"(r[3]) : "r"(a));
}
__device__ __forceinline__ void ldsm4t(uint32_t* r, uint32_t a) {
    asm volatile("ldmatrix.sync.aligned.m8n8.x4.trans.shared.b16 {%0,%1,%2,%3}, [%4];"
                 : "=r"(r[0]), "=r"(r[1]), "=r"(r[2]), "=r"(r[3]) : "r"(a));
}
__device__ __forceinline__ void mma4(float* c, const uint32_t* a, uint32_t b0, uint32_t b1) {
    asm volatile("mma.sync.aligned.m16n8k16.row.col.f32.f16.f16.f32 "
                 "{%0,%1,%2,%3}, {%4,%5,%6,%7}, {%8,%9}, {%0,%1,%2,%3};"
                 : "+f"(c[0]), "+f"(c[1]), "+f"(c[2]), "+f"(c[3])
                 : "r"(a[0]), "r"(a[1]), "r"(a[2]), "r"(a[3]), "r"(b0), "r"(b1));
}

// ---------------------------------------------------------------------------
// 0) reset output (after routing, before gemm2 — its only consumer)
// ---------------------------------------------------------------------------
__global__ void reset_kernel(float* __restrict__ out) {
    size_t i = (size_t)blockIdx.x * blockDim.x + threadIdx.x;
    out[i] = 0.0f;  // grid sized exactly T_TOK*HDIM
}

// ---------------------------------------------------------------------------
// 1) convert x (launch #1; also zeroes expert counters for this replay)
// ---------------------------------------------------------------------------
__global__ void convert_x_kernel(const float* __restrict__ x) {
    if (blockIdx.x == 0 && threadIdx.x < NEXP) g_cnt[threadIdx.x] = 0;
    size_t i = ((size_t)blockIdx.x * blockDim.x + threadIdx.x) * 8;
    float4 v0 = *reinterpret_cast<const float4*>(x + i);
    float4 v1 = *reinterpret_cast<const float4*>(x + i + 4);
    __half h[8];
    h[0] = __float2half_rn(v0.x); h[1] = __float2half_rn(v0.y);
    h[2] = __float2half_rn(v0.z); h[3] = __float2half_rn(v0.w);
    h[4] = __float2half_rn(v1.x); h[5] = __float2half_rn(v1.y);
    h[6] = __float2half_rn(v1.z); h[7] = __float2half_rn(v1.w);
    *reinterpret_cast<uint4*>(g_x + i) = *reinterpret_cast<uint4*>(h);
}

// ---------------------------------------------------------------------------
// 2) gate: top-2 + softmax in fp32 (exact routing)
// ---------------------------------------------------------------------------
__global__ void gate_kernel(const float* __restrict__ x, const float* __restrict__ gw) {
    int warp = threadIdx.x >> 5, lane = threadIdx.x & 31;
    int t = blockIdx.x * (blockDim.x >> 5) + warp;
    if (t >= T_TOK) return;
    float acc[NEXP];
#pragma unroll
    for (int e = 0; e < NEXP; e++) acc[e] = 0.0f;
    const float* xp = x + (size_t)t * HDIM;
    for (int h = lane; h < HDIM; h += 32) {
        float xv = xp[h];
#pragma unroll
        for (int e = 0; e < NEXP; e++) acc[e] += xv * gw[e * HDIM + h];
    }
#pragma unroll
    for (int e = 0; e < NEXP; e++)
#pragma unroll
        for (int o = 16; o > 0; o >>= 1)
            acc[e] += __shfl_xor_sync(0xffffffffu, acc[e], o);
    if (lane == 0) {
        int e0 = 0; float l0 = acc[0];
#pragma unroll
        for (int e = 1; e < NEXP; e++) if (acc[e] > l0) { l0 = acc[e]; e0 = e; }
        int e1 = -1; float l1 = -INFINITY;
#pragma unroll
        for (int e = 0; e < NEXP; e++) if (e != e0 && acc[e] > l1) { l1 = acc[e]; e1 = e; }
        float p = expf(l1 - l0);
        float s = 1.0f / (1.0f + p);
        g_eid[2 * t] = e0;  g_eid[2 * t + 1] = e1;
        g_wt [2 * t] = s;   g_wt [2 * t + 1] = p * s;
        atomicAdd(&g_cnt[e0], 1);
        atomicAdd(&g_cnt[e1], 1);
    }
}

__global__ void scan_kernel() {
    int s = 0;
    for (int e = 0; e < NEXP; e++) { g_off[e] = s; s += g_cnt[e]; g_fill[e] = 0; }
    g_off[NEXP] = s;
}

__global__ void scatter_kernel() {
    int t = blockIdx.x * blockDim.x + threadIdx.x;
    if (t >= T_TOK) return;
#pragma unroll
    for (int k = 0; k < TOPK; k++) {
        int e = g_eid[2 * t + k];
        int pos = g_off[e] + atomicAdd(&g_fill[e], 1);
        g_tok[pos] = t;
        g_w[pos]   = g_wt[2 * t + k];
    }
}

// ---------------------------------------------------------------------------
// 3) weight conversions: fp32 -> fp16
// ---------------------------------------------------------------------------
__global__ void convert_w1i_kernel(const float* __restrict__ w1) {
    size_t i = (size_t)blockIdx.x * blockDim.x + threadIdx.x; // over E*H*(F/4)
    size_t ek = i / (FDIM / 4);
    int f0 = (int)(i % (FDIM / 4)) * 4;
    const float* src = w1 + ek * (size_t)(2 * FDIM);
    float4 va = *reinterpret_cast<const float4*>(src + f0);
    float4 vb = *reinterpret_cast<const float4*>(src + FDIM + f0);
    __half h[8];
    h[0] = __float2half_rn(va.x); h[1] = __float2half_rn(vb.x);
    h[2] = __float2half_rn(va.y); h[3] = __float2half_rn(vb.y);
    h[4] = __float2half_rn(va.z); h[5] = __float2half_rn(vb.z);
    h[6] = __float2half_rn(va.w); h[7] = __float2half_rn(vb.w);
    size_t o = ek * (size_t)(2 * FDIM) + 2 * f0;
    *reinterpret_cast<uint4*>(g_w1i + o) = *reinterpret_cast<uint4*>(h);
}

__global__ void convert_w2s_kernel(const float* __restrict__ w2) {
    size_t i = ((size_t)blockIdx.x * blockDim.x + threadIdx.x) * 8;
    float4 v0 = *reinterpret_cast<const float4*>(w2 + i);
    float4 v1 = *reinterpret_cast<const float4*>(w2 + i + 4);
    __half h[8];
    h[0] = __float2half_rn(v0.x); h[1] = __float2half_rn(v0.y);
    h[2] = __float2half_rn(v0.z); h[3] = __float2half_rn(v0.w);
    h[4] = __float2half_rn(v1.x); h[5] = __float2half_rn(v1.y);
    h[6] = __float2half_rn(v1.z); h[7] = __float2half_rn(v1.w);
    *reinterpret_cast<uint4*>(g_w2s + i) = *reinterpret_cast<uint4*>(h);
}

// ---------------------------------------------------------------------------
// 4) grouped HMMA GEMM, fp16, 128x128x64, 3-stage cp.async, 2 CTAs/SM.
//    Warp grid 2x4 (wm in {0,1} -> 64 rows, wn in {0..3} -> 32 cols).
//    G1=true : D = gather(x) @ w1i, fused swiglu -> g_s
//    G1=false: Y = S @ w2,          weighted atomic scatter -> out
// ---------------------------------------------------------------------------
template<bool G1>
__global__ __launch_bounds__(256, 2) void gemm_tc(float* __restrict__ out) {
    constexpr int KDIM = G1 ? HDIM : FDIM;
    constexpr int NCH  = KDIM / BK;
    constexpr int LDB  = G1 ? (2 * FDIM) : HDIM;

    const int tid = threadIdx.x;
    const int e = blockIdx.z;
    const int row0 = g_off[e];
    const int nrows = g_off[e + 1] - row0;
    const int mbase = blockIdx.y * BM;
    if (mbase >= nrows) return;
    const int nbase = blockIdx.x * BN;

    extern __shared__ __align__(128) char dsm[];
    const uint32_t smem0 = (uint32_t)__cvta_generic_to_shared(dsm);

    // ---- loader setup (register-lean: bases + derived strides) ----
    // A: 128x64 fp16, 4 x 16B per thread; rows m = (tid>>3) + 32*r
    const __half* const Aroot = G1 ? g_x : g_s;
    uint32_t aoff[4], asz[4];
#pragma unroll
    for (int r = 0; r < 4; r++) {
        int m = (tid >> 3) + 32 * r;
        int gm = mbase + m;
        bool ok = gm < nrows;
        int rowid = ok ? (row0 + gm) : 0;
        uint32_t base;
        if (G1) {
            int tok = ok ? g_tok[rowid] : 0;
            base = (uint32_t)tok * HDIM;
        } else {
            base = (uint32_t)rowid * FDIM;
        }
        aoff[r] = base + (tid & 7) * 8;
        asz[r] = ok ? 16u : 0u;
    }
    const uint32_t adst0 = (uint32_t)((tid >> 3) * A_ROW_B + (tid & 7) * 16);
    // B: 64x128 fp16, 4 x 16B per thread; rows = (tid>>4) + 16*j
    const __half* const bbase = (G1 ? g_w1i : g_w2s) +
        ((size_t)e * KDIM + (tid >> 4)) * (size_t)LDB + nbase + (tid & 15) * 8;
    const uint32_t bdst0 = (uint32_t)(OFF_B + (tid >> 4) * B_ROW_B + (tid & 15) * 16);

    auto load_stage = [&](int ck) {
        uint32_t sb = smem0 + (ck % NSTAGE) * STAGE_B;
        uint32_t ka = (uint32_t)ck * BK;
        size_t kb = (size_t)ck * BK * LDB;
#pragma unroll
        for (int r = 0; r < 4; r++)
            cp16(sb + adst0 + r * (32 * A_ROW_B), Aroot + aoff[r] + ka, asz[r]);
#pragma unroll
        for (int j = 0; j < 4; j++)
            cp16(sb + bdst0 + j * (16 * B_ROW_B), bbase + kb + (size_t)j * 16 * LDB, 16u);
    };

    float c[4][4][4];
#pragma unroll
    for (int i = 0; i < 4; i++)
#pragma unroll
        for (int j = 0; j < 4; j++)
#pragma unroll
            for (int q = 0; q < 4; q++) c[i][j][q] = 0.0f;

    const int lane = tid & 31, wid = tid >> 5;
    const int wm = wid >> 2, wn = wid & 3;
    const int lr = lane & 15, lc = lane >> 4;

    load_stage(0); cp_commit();
    load_stage(1); cp_commit();

    for (int ck = 0; ck < NCH; ck++) {
        cp_wait1();
        __syncthreads();
        if (ck + 2 < NCH) load_stage(ck + 2);
        cp_commit();

        uint32_t sb = smem0 + (ck % NSTAGE) * STAGE_B;
#pragma unroll
        for (int ko = 0; ko < 4; ko++) {
            uint32_t aA = sb + (wm * 64 + lr) * A_ROW_B + ko * 32 + lc * 16;
            uint32_t aB = sb + OFF_B + (ko * 16 + lr) * B_ROW_B + wn * 64 + lc * 16;
            uint32_t a[4][4], b[2][4];
#pragma unroll
            for (int nj = 0; nj < 2; nj++) ldsm4t(b[nj], aB + nj * 32);
#pragma unroll
            for (int mi = 0; mi < 4; mi++) ldsm4(a[mi], aA + mi * 16 * A_ROW_B);
#pragma unroll
            for (int mi = 0; mi < 4; mi++)
#pragma unroll
                for (int nj = 0; nj < 2; nj++) {
                    mma4(c[mi][2 * nj],     a[mi], b[nj][0], b[nj][1]);
                    mma4(c[mi][2 * nj + 1], a[mi], b[nj][2], b[nj][3]);
                }
        }
    }
    cp_wait0();
    __syncthreads();   // compute done -> smem reusable for epilogue staging

    // ---- epilogue ----
    if constexpr (G1) {
        // swiglu on interleaved (a,b) pairs; stage 16 f-values/row via smem
        char* ep = dsm + wid * 64 * EPS;
        const int q = lane & 3, lrow = lane >> 2;
#pragma unroll
        for (int mi = 0; mi < 4; mi++) {
            int r0 = mi * 16 + lrow;
#pragma unroll
            for (int n8 = 0; n8 < 4; n8++) {
                int col = n8 * 4 + q;       // f-index within warp's 16
                float a0 = c[mi][n8][0], b0 = c[mi][n8][1];
                float a1 = c[mi][n8][2], b1 = c[mi][n8][3];
                float s0 = a0 / (1.0f + expf(-a0)) * b0;
                float s1 = a1 / (1.0f + expf(-a1)) * b1;
                *reinterpret_cast<__half*>(ep + r0 * EPS + col * 2) = __float2half_rn(s0);
                *reinterpret_cast<__half*>(ep + (r0 + 8) * EPS + col * 2) = __float2half_rn(s1);
            }
        }
        __syncwarp();
        const int fb = (nbase >> 1) + wn * 16;
        const int q2 = lane & 1, hrow = lane >> 1;   // 16 rows x 2 halves per pass
#pragma unroll
        for (int j = 0; j < 4; j++) {
            int row = j * 16 + hrow;
            int gm = mbase + wm * 64 + row;
            if (gm < nrows) {
                uint4 v = *reinterpret_cast<const uint4*>(ep + row * EPS + q2 * 16);
                *reinterpret_cast<uint4*>(
                    &g_s[(size_t)(row0 + gm) * FDIM + fb + q2 * 8]) = v;
            }
        }
    } else {
        const int q = lane & 3, lrow = lane >> 2;
#pragma unroll
        for (int mi = 0; mi < 4; mi++) {
            int r0 = wm * 64 + mi * 16 + lrow;
            int gm0 = mbase + r0, gm1 = gm0 + 8;
            bool ok0 = gm0 < nrows, ok1 = gm1 < nrows;
            int tok0 = ok0 ? g_tok[row0 + gm0] : 0;
            int tok1 = ok1 ? g_tok[row0 + gm1] : 0;
            float w0 = ok0 ? g_w[row0 + gm0] : 0.0f;
            float w1v = ok1 ? g_w[row0 + gm1] : 0.0f;
            float* o0 = out + (size_t)tok0 * HDIM;
            float* o1 = out + (size_t)tok1 * HDIM;
#pragma unroll
            for (int n8 = 0; n8 < 4; n8++) {
                int col = nbase + wn * 32 + n8 * 8 + q * 2;
                if (ok0) {
                    atomicAdd(o0 + col,     w0 * c[mi][n8][0]);
                    atomicAdd(o0 + col + 1, w0 * c[mi][n8][1]);
                }
                if (ok1) {
                    atomicAdd(o1 + col,     w1v * c[mi][n8][2]);
                    atomicAdd(o1 + col + 1, w1v * c[mi][n8][3]);
                }
            }
        }
    }
}

// ---------------------------------------------------------------------------
// launch — gemm_tc<true> is the 6th launch (ncu -s 5 -c 1 target)
// ---------------------------------------------------------------------------
extern "C" void kernel_launch(void* const* d_in, const int* in_sizes, int n_in,
                              void* d_out, int out_size) {
    const float* x  = (const float*)d_in[0]; // [T, H]
    const float* gw = (const float*)d_in[1]; // [E, H]
    const float* w1 = (const float*)d_in[2]; // [E, H, 2F]
    const float* w2 = (const float*)d_in[3]; // [E, F, H]
    float* out = (float*)d_out;              // [T, H]

    cudaFuncSetAttribute(gemm_tc<true>,  cudaFuncAttributeMaxDynamicSharedMemorySize, SMEM_TOTAL);
    cudaFuncSetAttribute(gemm_tc<false>, cudaFuncAttributeMaxDynamicSharedMemorySize, SMEM_TOTAL);

    // #1: x conversion (+ counter zeroing)
    convert_x_kernel<<<(T_TOK * HDIM / 8) / 256, 256>>>(x);
    // #2-#4: routing
    gate_kernel<<<T_TOK / 8, 256>>>(x, gw);
    scan_kernel<<<1, 1>>>();
    scatter_kernel<<<T_TOK / 256, 256>>>();
    // #5: w1 conversion
    convert_w1i_kernel<<<(NEXP * HDIM * (FDIM / 4)) / 256, 256>>>(w1);
    // #6: GEMM1 (ncu capture target)
    gemm_tc<true ><<<dim3(2 * FDIM / BN, MTILES_MAX, NEXP), 256, SMEM_TOTAL>>>(out);
    // #7-#8: out reset + w2 conversion
    reset_kernel<<<8192, 1024>>>(out);
    convert_w2s_kernel<<<(int)(((size_t)NEXP * FDIM * HDIM / 8) / 256), 256>>>(w2);
    // #9: GEMM2
    gemm_tc<false><<<dim3(HDIM / BN, MTILES_MAX, NEXP), 256, SMEM_TOTAL>>>(out);
}

// round 9
// speedup vs baseline: 1.0893x; 1.0028x over previous
#include <cuda_runtime.h>
#include <cuda_fp16.h>
#include <cstdint>
#include <math.h>

// Problem constants
#define T_TOK 4096
#define HDIM  2048
#define FDIM  4096
#define NEXP  8
#define TOPK  2
#define NASSIGN (T_TOK * TOPK)   // 8192

// GEMM tiling: 128x128x64, 2 CTAs/SM
#define BM 128
#define BN 128
#define BK 64
#define MTILES_MAX 16

#define A_ROW_B 144              // 64 fp16 = 128B + 16B pad
#define B_ROW_B 272              // 128 fp16 = 256B + 16B pad
#define OFF_B   (BM * A_ROW_B)               // 18432
#define STAGE_B (OFF_B + BK * B_ROW_B)       // 35840
#define NSTAGE  3
#define SMEM_TOTAL (NSTAGE * STAGE_B)        // 107520 -> 2 CTAs/SM
#define EPS 48                   // G1 epilogue smem row stride (32B data + 16 pad)

// ---------------------------------------------------------------------------
// Scratch
// ---------------------------------------------------------------------------
__device__ __half g_x[(size_t)T_TOK * HDIM];
// w1 fp16, column-interleaved: [E][H][2F], col n' = 2f -> a_f, 2f+1 -> b_f
__device__ __half g_w1i[(size_t)NEXP * HDIM * 2 * FDIM];
// w2 fp16, natural layout [E][F][H]
__device__ __half g_w2s[(size_t)NEXP * FDIM * HDIM];
// swiglu output fp16: [NASSIGN][F]
__device__ __half g_s[(size_t)NASSIGN * FDIM];

__device__ int   g_eid[T_TOK * TOPK];
__device__ float g_wt [T_TOK * TOPK];
__device__ int   g_tok[NASSIGN];
__device__ float g_w  [NASSIGN];
__device__ int   g_cnt [NEXP];
__device__ int   g_off [NEXP + 1];
__device__ int   g_fill[NEXP];

// ---------------------------------------------------------------------------
// PTX helpers (base ISA only)
// ---------------------------------------------------------------------------
__device__ __forceinline__ void cp16(uint32_t dst, const void* src, uint32_t sz) {
    asm volatile("cp.async.cg.shared.global [%0], [%1], 16, %2;"
                 :: "r"(dst), "l"(src), "r"(sz) : "memory");
}
__device__ __forceinline__ void cp_commit() {
    asm volatile("cp.async.commit_group;" ::: "memory");
}
__device__ __forceinline__ void cp_wait1() {
    asm volatile("cp.async.wait_group 1;" ::: "memory");
}
__device__ __forceinline__ void cp_wait0() {
    asm volatile("cp.async.wait_group 0;" ::: "memory");
}
__device__ __forceinline__ void ldsm4(uint32_t* r, uint32_t a) {
    asm volatile("ldmatrix.sync.aligned.m8n8.x4.shared.b16 {%0,%1,%2,%3}, [%4];"
                 : "=r"(r[0]), "=r"(r[1]), "=r"(r[2]), "=r"(r[3]) : "r"(a));
}
__device__ __forceinline__ void ldsm4t(uint32_t* r, uint32_t a) {
    asm volatile("ldmatrix.sync.aligned.m8n8.x4.trans.shared.b16 {%0,%1,%2,%3}, [%4];"
                 : "=r"(r[0]), "=r"(r[1]), "=r"(r[2]), "=r"(r[3]) : "r"(a));
}
__device__ __forceinline__ void mma4(float* c, const uint32_t* a, uint32_t b0, uint32_t b1) {
    asm volatile("mma.sync.aligned.m16n8k16.row.col.f32.f16.f16.f32 "
                 "{%0,%1,%2,%3}, {%4,%5,%6,%7}, {%8,%9}, {%0,%1,%2,%3};"
                 : "+f"(c[0]), "+f"(c[1]), "+f"(c[2]), "+f"(c[3])
                 : "r"(a[0]), "r"(a[1]), "r"(a[2]), "r"(a[3]), "r"(b0), "r"(b1));
}

// ---------------------------------------------------------------------------
// 0) reset output (after routing, before gemm2 — its only consumer)
// ---------------------------------------------------------------------------
__global__ void reset_kernel(float* __restrict__ out) {
    size_t i = (size_t)blockIdx.x * blockDim.x + threadIdx.x;
    out[i] = 0.0f;  // grid sized exactly T_TOK*HDIM
}

// ---------------------------------------------------------------------------
// 1) convert x (launch #1; also zeroes expert counters for this replay)
// ---------------------------------------------------------------------------
__global__ void convert_x_kernel(const float* __restrict__ x) {
    if (blockIdx.x == 0 && threadIdx.x < NEXP) g_cnt[threadIdx.x] = 0;
    size_t i = ((size_t)blockIdx.x * blockDim.x + threadIdx.x) * 8;
    float4 v0 = *reinterpret_cast<const float4*>(x + i);
    float4 v1 = *reinterpret_cast<const float4*>(x + i + 4);
    __half h[8];
    h[0] = __float2half_rn(v0.x); h[1] = __float2half_rn(v0.y);
    h[2] = __float2half_rn(v0.z); h[3] = __float2half_rn(v0.w);
    h[4] = __float2half_rn(v1.x); h[5] = __float2half_rn(v1.y);
    h[6] = __float2half_rn(v1.z); h[7] = __float2half_rn(v1.w);
    *reinterpret_cast<uint4*>(g_x + i) = *reinterpret_cast<uint4*>(h);
}

// ---------------------------------------------------------------------------
// 2) gate: top-2 + softmax in fp32 (exact routing)
// ---------------------------------------------------------------------------
__global__ void gate_kernel(const float* __restrict__ x, const float* __restrict__ gw) {
    int warp = threadIdx.x >> 5, lane = threadIdx.x & 31;
    int t = blockIdx.x * (blockDim.x >> 5) + warp;
    if (t >= T_TOK) return;
    float acc[NEXP];
#pragma unroll
    for (int e = 0; e < NEXP; e++) acc[e] = 0.0f;
    const float* xp = x + (size_t)t * HDIM;
    for (int h = lane; h < HDIM; h += 32) {
        float xv = xp[h];
#pragma unroll
        for (int e = 0; e < NEXP; e++) acc[e] += xv * gw[e * HDIM + h];
    }
#pragma unroll
    for (int e = 0; e < NEXP; e++)
#pragma unroll
        for (int o = 16; o > 0; o >>= 1)
            acc[e] += __shfl_xor_sync(0xffffffffu, acc[e], o);
    if (lane == 0) {
        int e0 = 0; float l0 = acc[0];
#pragma unroll
        for (int e = 1; e < NEXP; e++) if (acc[e] > l0) { l0 = acc[e]; e0 = e; }
        int e1 = -1; float l1 = -INFINITY;
#pragma unroll
        for (int e = 0; e < NEXP; e++) if (e != e0 && acc[e] > l1) { l1 = acc[e]; e1 = e; }
        float p = expf(l1 - l0);
        float s = 1.0f / (1.0f + p);
        g_eid[2 * t] = e0;  g_eid[2 * t + 1] = e1;
        g_wt [2 * t] = s;   g_wt [2 * t + 1] = p * s;
        atomicAdd(&g_cnt[e0], 1);
        atomicAdd(&g_cnt[e1], 1);
    }
}

__global__ void scan_kernel() {
    int s = 0;
    for (int e = 0; e < NEXP; e++) { g_off[e] = s; s += g_cnt[e]; g_fill[e] = 0; }
    g_off[NEXP] = s;
}

__global__ void scatter_kernel() {
    int t = blockIdx.x * blockDim.x + threadIdx.x;
    if (t >= T_TOK) return;
#pragma unroll
    for (int k = 0; k < TOPK; k++) {
        int e = g_eid[2 * t + k];
        int pos = g_off[e] + atomicAdd(&g_fill[e], 1);
        g_tok[pos] = t;
        g_w[pos]   = g_wt[2 * t + k];
    }
}

// ---------------------------------------------------------------------------
// 3) weight conversions: fp32 -> fp16
// ---------------------------------------------------------------------------
__global__ void convert_w1i_kernel(const float* __restrict__ w1) {
    size_t i = (size_t)blockIdx.x * blockDim.x + threadIdx.x; // over E*H*(F/4)
    size_t ek = i / (FDIM / 4);
    int f0 = (int)(i % (FDIM / 4)) * 4;
    const float* src = w1 + ek * (size_t)(2 * FDIM);
    float4 va = *reinterpret_cast<const float4*>(src + f0);
    float4 vb = *reinterpret_cast<const float4*>(src + FDIM + f0);
    __half h[8];
    h[0] = __float2half_rn(va.x); h[1] = __float2half_rn(vb.x);
    h[2] = __float2half_rn(va.y); h[3] = __float2half_rn(vb.y);
    h[4] = __float2half_rn(va.z); h[5] = __float2half_rn(vb.z);
    h[6] = __float2half_rn(va.w); h[7] = __float2half_rn(vb.w);
    size_t o = ek * (size_t)(2 * FDIM) + 2 * f0;
    *reinterpret_cast<uint4*>(g_w1i + o) = *reinterpret_cast<uint4*>(h);
}

__global__ void convert_w2s_kernel(const float* __restrict__ w2) {
    size_t i = ((size_t)blockIdx.x * blockDim.x + threadIdx.x) * 8;
    float4 v0 = *reinterpret_cast<const float4*>(w2 + i);
    float4 v1 = *reinterpret_cast<const float4*>(w2 + i + 4);
    __half h[8];
    h[0] = __float2half_rn(v0.x); h[1] = __float2half_rn(v0.y);
    h[2] = __float2half_rn(v0.z); h[3] = __float2half_rn(v0.w);
    h[4] = __float2half_rn(v1.x); h[5] = __float2half_rn(v1.y);
    h[6] = __float2half_rn(v1.z); h[7] = __float2half_rn(v1.w);
    *reinterpret_cast<uint4*>(g_w2s + i) = *reinterpret_cast<uint4*>(h);
}

// ---------------------------------------------------------------------------
// 4) grouped HMMA GEMM, fp16, 128x128x64, 3-stage cp.async, 2 CTAs/SM.
//    Warp grid 2x4 (wm in {0,1} -> 64 rows, wn in {0..3} -> 32 cols).
//    G1=true : D = gather(x) @ w1i, fused swiglu -> g_s
//    G1=false: Y = S @ w2,          weighted atomic scatter -> out
// ---------------------------------------------------------------------------
template<bool G1>
__global__ __launch_bounds__(256, 2) void gemm_tc(float* __restrict__ out) {
    constexpr int KDIM = G1 ? HDIM : FDIM;
    constexpr int NCH  = KDIM / BK;
    constexpr int LDB  = G1 ? (2 * FDIM) : HDIM;

    const int tid = threadIdx.x;
    const int e = blockIdx.z;
    const int row0 = g_off[e];
    const int nrows = g_off[e + 1] - row0;
    const int mbase = blockIdx.y * BM;
    if (mbase >= nrows) return;
    const int nbase = blockIdx.x * BN;

    extern __shared__ __align__(128) char dsm[];
    const uint32_t smem0 = (uint32_t)__cvta_generic_to_shared(dsm);

    // ---- loader setup (register-lean: bases + derived strides) ----
    // A: 128x64 fp16, 4 x 16B per thread; rows m = (tid>>3) + 32*r
    const __half* const Aroot = G1 ? g_x : g_s;
    uint32_t aoff[4], asz[4];
#pragma unroll
    for (int r = 0; r < 4; r++) {
        int m = (tid >> 3) + 32 * r;
        int gm = mbase + m;
        bool ok = gm < nrows;
        int rowid = ok ? (row0 + gm) : 0;
        uint32_t base;
        if (G1) {
            int tok = ok ? g_tok[rowid] : 0;
            base = (uint32_t)tok * HDIM;
        } else {
            base = (uint32_t)rowid * FDIM;
        }
        aoff[r] = base + (tid & 7) * 8;
        asz[r] = ok ? 16u : 0u;
    }
    const uint32_t adst0 = (uint32_t)((tid >> 3) * A_ROW_B + (tid & 7) * 16);
    // B: 64x128 fp16, 4 x 16B per thread; rows = (tid>>4) + 16*j
    const __half* const bbase = (G1 ? g_w1i : g_w2s) +
        ((size_t)e * KDIM + (tid >> 4)) * (size_t)LDB + nbase + (tid & 15) * 8;
    const uint32_t bdst0 = (uint32_t)(OFF_B + (tid >> 4) * B_ROW_B + (tid & 15) * 16);

    auto load_stage = [&](int ck) {
        uint32_t sb = smem0 + (ck % NSTAGE) * STAGE_B;
        uint32_t ka = (uint32_t)ck * BK;
        size_t kb = (size_t)ck * BK * LDB;
#pragma unroll
        for (int r = 0; r < 4; r++)
            cp16(sb + adst0 + r * (32 * A_ROW_B), Aroot + aoff[r] + ka, asz[r]);
#pragma unroll
        for (int j = 0; j < 4; j++)
            cp16(sb + bdst0 + j * (16 * B_ROW_B), bbase + kb + (size_t)j * 16 * LDB, 16u);
    };

    float c[4][4][4];
#pragma unroll
    for (int i = 0; i < 4; i++)
#pragma unroll
        for (int j = 0; j < 4; j++)
#pragma unroll
            for (int q = 0; q < 4; q++) c[i][j][q] = 0.0f;

    const int lane = tid & 31, wid = tid >> 5;
    const int wm = wid >> 2, wn = wid & 3;
    const int lr = lane & 15, lc = lane >> 4;

    load_stage(0); cp_commit();
    load_stage(1); cp_commit();

    for (int ck = 0; ck < NCH; ck++) {
        cp_wait1();
        __syncthreads();
        if (ck + 2 < NCH) load_stage(ck + 2);
        cp_commit();

        uint32_t sb = smem0 + (ck % NSTAGE) * STAGE_B;
#pragma unroll
        for (int ko = 0; ko < 4; ko++) {
            uint32_t aA = sb + (wm * 64 + lr) * A_ROW_B + ko * 32 + lc * 16;
            uint32_t aB = sb + OFF_B + (ko * 16 + lr) * B_ROW_B + wn * 64 + lc * 16;
            uint32_t a[4][4], b[2][4];
#pragma unroll
            for (int nj = 0; nj < 2; nj++) ldsm4t(b[nj], aB + nj * 32);
#pragma unroll
            for (int mi = 0; mi < 4; mi++) ldsm4(a[mi], aA + mi * 16 * A_ROW_B);
#pragma unroll
            for (int mi = 0; mi < 4; mi++)
#pragma unroll
                for (int nj = 0; nj < 2; nj++) {
                    mma4(c[mi][2 * nj],     a[mi], b[nj][0], b[nj][1]);
                    mma4(c[mi][2 * nj + 1], a[mi], b[nj][2], b[nj][3]);
                }
        }
    }
    cp_wait0();
    __syncthreads();   // compute done -> smem reusable for epilogue staging

    // ---- epilogue ----
    if constexpr (G1) {
        // swiglu on interleaved (a,b) pairs; stage 16 f-values/row via smem
        char* ep = dsm + wid * 64 * EPS;
        const int q = lane & 3, lrow = lane >> 2;
#pragma unroll
        for (int mi = 0; mi < 4; mi++) {
            int r0 = mi * 16 + lrow;
#pragma unroll
            for (int n8 = 0; n8 < 4; n8++) {
                int col = n8 * 4 + q;       // f-index within warp's 16
                float a0 = c[mi][n8][0], b0 = c[mi][n8][1];
                float a1 = c[mi][n8][2], b1 = c[mi][n8][3];
                float s0 = a0 / (1.0f + expf(-a0)) * b0;
                float s1 = a1 / (1.0f + expf(-a1)) * b1;
                *reinterpret_cast<__half*>(ep + r0 * EPS + col * 2) = __float2half_rn(s0);
                *reinterpret_cast<__half*>(ep + (r0 + 8) * EPS + col * 2) = __float2half_rn(s1);
            }
        }
        __syncwarp();
        const int fb = (nbase >> 1) + wn * 16;
        const int q2 = lane & 1, hrow = lane >> 1;   // 16 rows x 2 halves per pass
#pragma unroll
        for (int j = 0; j < 4; j++) {
            int row = j * 16 + hrow;
            int gm = mbase + wm * 64 + row;
            if (gm < nrows) {
                uint4 v = *reinterpret_cast<const uint4*>(ep + row * EPS + q2 * 16);
                *reinterpret_cast<uint4*>(
                    &g_s[(size_t)(row0 + gm) * FDIM + fb + q2 * 8]) = v;
            }
        }
    } else {
        const int q = lane & 3, lrow = lane >> 2;
#pragma unroll
        for (int mi = 0; mi < 4; mi++) {
            int r0 = wm * 64 + mi * 16 + lrow;
            int gm0 = mbase + r0, gm1 = gm0 + 8;
            bool ok0 = gm0 < nrows, ok1 = gm1 < nrows;
            int tok0 = ok0 ? g_tok[row0 + gm0] : 0;
            int tok1 = ok1 ? g_tok[row0 + gm1] : 0;
            float w0 = ok0 ? g_w[row0 + gm0] : 0.0f;
            float w1v = ok1 ? g_w[row0 + gm1] : 0.0f;
            float* o0 = out + (size_t)tok0 * HDIM;
            float* o1 = out + (size_t)tok1 * HDIM;
#pragma unroll
            for (int n8 = 0; n8 < 4; n8++) {
                int col = nbase + wn * 32 + n8 * 8 + q * 2;
                if (ok0) {
                    atomicAdd(o0 + col,     w0 * c[mi][n8][0]);
                    atomicAdd(o0 + col + 1, w0 * c[mi][n8][1]);
                }
                if (ok1) {
                    atomicAdd(o1 + col,     w1v * c[mi][n8][2]);
                    atomicAdd(o1 + col + 1, w1v * c[mi][n8][3]);
                }
            }
        }
    }
}

// ---------------------------------------------------------------------------
// launch — gemm_tc<true> is the 6th launch (ncu -s 5 -c 1 target)
// ---------------------------------------------------------------------------
extern "C" void kernel_launch(void* const* d_in, const int* in_sizes, int n_in,
                              void* d_out, int out_size) {
    const float* x  = (const float*)d_in[0]; // [T, H]
    const float* gw = (const float*)d_in[1]; // [E, H]
    const float* w1 = (const float*)d_in[2]; // [E, H, 2F]
    const float* w2 = (const float*)d_in[3]; // [E, F, H]
    float* out = (float*)d_out;              // [T, H]

    cudaFuncSetAttribute(gemm_tc<true>,  cudaFuncAttributeMaxDynamicSharedMemorySize, SMEM_TOTAL);
    cudaFuncSetAttribute(gemm_tc<false>, cudaFuncAttributeMaxDynamicSharedMemorySize, SMEM_TOTAL);

    // #1: x conversion (+ counter zeroing)
    convert_x_kernel<<<(T_TOK * HDIM / 8) / 256, 256>>>(x);
    // #2-#4: routing
    gate_kernel<<<T_TOK / 8, 256>>>(x, gw);
    scan_kernel<<<1, 1>>>();
    scatter_kernel<<<T_TOK / 256, 256>>>();
    // #5: w1 conversion
    convert_w1i_kernel<<<(NEXP * HDIM * (FDIM / 4)) / 256, 256>>>(w1);
    // #6: GEMM1 (ncu capture target)
    gemm_tc<true ><<<dim3(2 * FDIM / BN, MTILES_MAX, NEXP), 256, SMEM_TOTAL>>>(out);
    // #7-#8: out reset + w2 conversion
    reset_kernel<<<8192, 1024>>>(out);
    convert_w2s_kernel<<<(int)(((size_t)NEXP * FDIM * HDIM / 8) / 256), 256>>>(w2);
    // #9: GEMM2
    gemm_tc<false><<<dim3(HDIM / BN, MTILES_MAX, NEXP), 256, SMEM_TOTAL>>>(out);
}